// round 2
// baseline (speedup 1.0000x reference)
#include <cuda_runtime.h>
#include <cuda_bf16.h>
#include <cstdint>
#include <cstddef>

// Problem constants
#define BATCH    16384
#define EMB      64
#define NSP      26
#define NFEAT    28           // user + item + 26 sparse
#define KDIM     1792         // EMB * NFEAT
#define NDIM     128          // HIDDEN
#define SPVOC    100000
#define TILE_M   64
#define NTHREADS 128          // 4 warps, each owns 16 rows x 128 cols
#define AS_STR   72           // 64 + 8 bf16 pad to kill smem bank conflicts

// Pre-transposed bf16 copy of W1: g_W1T[n][k]  (n-major, k contiguous)
__device__ __nv_bfloat16 g_W1T[NDIM * KDIM];

__global__ void prep_w1_kernel(const float* __restrict__ W1) {
    int i = blockIdx.x * blockDim.x + threadIdx.x;
    if (i < NDIM * KDIM) {
        int n = i / KDIM;
        int k = i - n * KDIM;
        g_W1T[i] = __float2bfloat16(W1[(size_t)k * NDIM + n]);
    }
}

__global__ __launch_bounds__(NTHREADS) void dlrm_fused_kernel(
    const int*   __restrict__ user_ids,
    const int*   __restrict__ item_ids,
    const int*   __restrict__ sparse,
    const float* __restrict__ user_emb,
    const float* __restrict__ item_emb,
    const float* __restrict__ sparse_tables,
    const float* __restrict__ b1,
    const float* __restrict__ W2,
    const float* __restrict__ b2,
    float*       __restrict__ out)
{
    __shared__ __nv_bfloat16 As[TILE_M][AS_STR];   // gathered rows, bf16
    __shared__ __nv_bfloat16 Bs[NDIM][AS_STR];     // W1T k-tile, n-major

    const int tid  = threadIdx.x;
    const int warp = tid >> 5;
    const int lane = tid & 31;
    const int row0 = blockIdx.x * TILE_M;

    // accumulators: warp covers 16 rows x 128 cols = 16 m16n8 tiles
    float c[16][4];
    #pragma unroll
    for (int nt = 0; nt < 16; ++nt) {
        c[nt][0] = 0.f; c[nt][1] = 0.f; c[nt][2] = 0.f; c[nt][3] = 0.f;
    }

    const int g  = lane >> 2;   // 0..7
    const int tg = lane & 3;    // 0..3
    const int mrow = warp * 16;

    for (int f = 0; f < NFEAT; ++f) {
        // ---- Stage A: gather one embedding feature for 64 rows -> bf16 smem
        // 64 rows * 16 float4-chunks = 1024 work items / 128 threads = 8 each
        #pragma unroll
        for (int i = 0; i < 8; ++i) {
            int linear = tid + i * NTHREADS;
            int r  = linear >> 4;     // local row
            int ch = linear & 15;     // float4 chunk (4 floats)
            int grow = row0 + r;
            const float* src;
            if (f == 0) {
                src = user_emb + (size_t)__ldg(user_ids + grow) * EMB;
            } else if (f == 1) {
                src = item_emb + (size_t)__ldg(item_ids + grow) * EMB;
            } else {
                int idx = __ldg(sparse + (size_t)grow * NSP + (f - 2));
                src = sparse_tables + ((size_t)(f - 2) * SPVOC + (size_t)idx) * EMB;
            }
            float4 v = __ldg((const float4*)src + ch);
            __nv_bfloat162 p0 = __floats2bfloat162_rn(v.x, v.y);
            __nv_bfloat162 p1 = __floats2bfloat162_rn(v.z, v.w);
            *(__nv_bfloat162*)&As[r][ch * 4]     = p0;
            *(__nv_bfloat162*)&As[r][ch * 4 + 2] = p1;
        }

        // ---- Stage B: load W1T k-tile [128 n][64 k] bf16 (L2-resident)
        // 128 n * 8 uint4-chunks = 1024 / 128 threads = 8 each
        const int kbase = f * EMB;
        #pragma unroll
        for (int i = 0; i < 8; ++i) {
            int linear = tid + i * NTHREADS;
            int n  = linear >> 3;
            int ch = linear & 7;
            uint4 v = *(const uint4*)&g_W1T[(size_t)n * KDIM + kbase + ch * 8];
            *(uint4*)&Bs[n][ch * 8] = v;
        }
        __syncthreads();

        // ---- MMA: 4 k-steps of m16n8k16 bf16 across 16 n-tiles
        #pragma unroll
        for (int ks = 0; ks < 4; ++ks) {
            uint32_t a0 = *(const uint32_t*)&As[mrow + g    ][ks * 16 + 2 * tg];
            uint32_t a1 = *(const uint32_t*)&As[mrow + g + 8][ks * 16 + 2 * tg];
            uint32_t a2 = *(const uint32_t*)&As[mrow + g    ][ks * 16 + 2 * tg + 8];
            uint32_t a3 = *(const uint32_t*)&As[mrow + g + 8][ks * 16 + 2 * tg + 8];
            #pragma unroll
            for (int nt = 0; nt < 16; ++nt) {
                uint32_t b0  = *(const uint32_t*)&Bs[nt * 8 + g][ks * 16 + 2 * tg];
                uint32_t b1r = *(const uint32_t*)&Bs[nt * 8 + g][ks * 16 + 2 * tg + 8];
                asm volatile(
                    "mma.sync.aligned.m16n8k16.row.col.f32.bf16.bf16.f32 "
                    "{%0,%1,%2,%3}, {%4,%5,%6,%7}, {%8,%9}, {%0,%1,%2,%3};\n"
                    : "+f"(c[nt][0]), "+f"(c[nt][1]), "+f"(c[nt][2]), "+f"(c[nt][3])
                    : "r"(a0), "r"(a1), "r"(a2), "r"(a3), "r"(b0), "r"(b1r));
            }
        }
        __syncthreads();
    }

    // ---- Epilogue: bias + ReLU + dot with W2 + bias2 + sigmoid
    float acc0 = 0.f, acc1 = 0.f;   // rows (mrow+g) and (mrow+g+8)
    #pragma unroll
    for (int nt = 0; nt < 16; ++nt) {
        int n0 = nt * 8 + 2 * tg;
        float bias0 = __ldg(b1 + n0);
        float bias1 = __ldg(b1 + n0 + 1);
        float w0 = __ldg(W2 + n0);
        float w1 = __ldg(W2 + n0 + 1);
        acc0 += fmaxf(c[nt][0] + bias0, 0.f) * w0;
        acc0 += fmaxf(c[nt][1] + bias1, 0.f) * w1;
        acc1 += fmaxf(c[nt][2] + bias0, 0.f) * w0;
        acc1 += fmaxf(c[nt][3] + bias1, 0.f) * w1;
    }
    // reduce the 4 lanes of each row-group (lanes g*4 .. g*4+3)
    acc0 += __shfl_xor_sync(0xffffffffu, acc0, 1);
    acc0 += __shfl_xor_sync(0xffffffffu, acc0, 2);
    acc1 += __shfl_xor_sync(0xffffffffu, acc1, 1);
    acc1 += __shfl_xor_sync(0xffffffffu, acc1, 2);

    if (tg == 0) {
        float bb = __ldg(b2);
        int r = row0 + mrow + g;
        float x0 = acc0 + bb;
        float x1 = acc1 + bb;
        out[r]     = 1.f / (1.f + __expf(-x0));
        out[r + 8] = 1.f / (1.f + __expf(-x1));
    }
}

extern "C" void kernel_launch(void* const* d_in, const int* in_sizes, int n_in,
                              void* d_out, int out_size) {
    const int*   user_ids      = (const int*)d_in[0];
    const int*   item_ids      = (const int*)d_in[1];
    const int*   sparse        = (const int*)d_in[2];
    const float* user_emb      = (const float*)d_in[3];
    const float* item_emb      = (const float*)d_in[4];
    const float* sparse_tables = (const float*)d_in[5];
    const float* W1            = (const float*)d_in[6];
    const float* b1            = (const float*)d_in[7];
    const float* W2            = (const float*)d_in[8];
    const float* b2            = (const float*)d_in[9];
    float* out = (float*)d_out;

    prep_w1_kernel<<<(NDIM * KDIM + 255) / 256, 256>>>(W1);
    dlrm_fused_kernel<<<BATCH / TILE_M, NTHREADS>>>(
        user_ids, item_ids, sparse, user_emb, item_emb, sparse_tables,
        b1, W2, b2, out);
}

// round 5
// speedup vs baseline: 2.8483x; 2.8483x over previous
#include <cuda_runtime.h>
#include <cuda_bf16.h>
#include <cstdint>
#include <cstddef>

// Problem constants
#define BATCH    16384
#define EMB      64
#define NSP      26
#define NFEAT    28           // user + item + 26 sparse
#define KDIM     1792         // EMB * NFEAT
#define NDIM     128          // HIDDEN
#define SPVOC    100000
#define TILE_M   64
#define NTHREADS 256          // 8 warps: (warp&3)=row group, (warp>>2)=n half
#define A_STR    68           // fp32 row stride (64 + 4 pad, keeps 16B cp.async align)
#define B_STR    72           // bf16 row stride (64 + 8 pad, conflict-free b-frag loads)

#define SMEM_A_BYTES   (2 * TILE_M * A_STR * 4)          // 34816
#define SMEM_B_BYTES   (2 * NDIM * B_STR * 2)            // 36864
#define SMEM_IDX_BYTES (TILE_M * NFEAT * 4)              // 7168
#define SMEM_PART_BYTES (TILE_M * 2 * 4)                 // 512
#define SMEM_TOTAL (SMEM_A_BYTES + SMEM_B_BYTES + SMEM_IDX_BYTES + SMEM_PART_BYTES)

// Pre-transposed bf16 copy of W1: g_W1T[n][k]  (n-major, k contiguous)
__device__ __nv_bfloat16 g_W1T[NDIM * KDIM];

__global__ void prep_w1_kernel(const float* __restrict__ W1) {
    int i = blockIdx.x * blockDim.x + threadIdx.x;
    if (i < NDIM * KDIM) {
        int n = i / KDIM;
        int k = i - n * KDIM;
        g_W1T[i] = __float2bfloat16(W1[(size_t)k * NDIM + n]);
    }
}

__device__ __forceinline__ void cpa16(void* smem, const void* gmem) {
    uint32_t s = (uint32_t)__cvta_generic_to_shared(smem);
    asm volatile("cp.async.cg.shared.global [%0], [%1], 16;\n" :: "r"(s), "l"(gmem));
}
__device__ __forceinline__ void cpa_commit() {
    asm volatile("cp.async.commit_group;\n" ::: "memory");
}
__device__ __forceinline__ void cpa_wait1() {
    asm volatile("cp.async.wait_group 1;\n" ::: "memory");
}
__device__ __forceinline__ void cpa_wait0() {
    asm volatile("cp.async.wait_group 0;\n" ::: "memory");
}

__device__ __forceinline__ uint32_t pack_bf16x2(float x, float y) {
    __nv_bfloat162 h = __floats2bfloat162_rn(x, y);
    return *(uint32_t*)&h;
}

__global__ __launch_bounds__(NTHREADS, 2) void dlrm_fused_kernel(
    const int*   __restrict__ user_ids,
    const int*   __restrict__ item_ids,
    const int*   __restrict__ sparse,
    const float* __restrict__ user_emb,
    const float* __restrict__ item_emb,
    const float* __restrict__ sparse_tables,
    const float* __restrict__ b1,
    const float* __restrict__ W2,
    const float* __restrict__ b2,
    float*       __restrict__ out)
{
    extern __shared__ char smem_raw[];
    float*         sA    = (float*)smem_raw;                         // [2][TILE_M][A_STR] fp32
    __nv_bfloat16* sB    = (__nv_bfloat16*)(smem_raw + SMEM_A_BYTES);// [2][NDIM][B_STR] bf16
    int*           sIdx  = (int*)(smem_raw + SMEM_A_BYTES + SMEM_B_BYTES);  // [TILE_M][NFEAT]
    float*         sPart = (float*)(smem_raw + SMEM_A_BYTES + SMEM_B_BYTES + SMEM_IDX_BYTES);

    const int tid  = threadIdx.x;
    const int warp = tid >> 5;
    const int lane = tid & 31;
    const int row0 = blockIdx.x * TILE_M;

    const int g    = lane >> 2;       // 0..7
    const int tg   = lane & 3;        // 0..3
    const int mrow = (warp & 3) * 16; // row group
    const int nh   = warp >> 2;       // 0/1: n half (64 cols each)

    // ---- Preload ALL indices for this CTA's 64 rows into SMEM (one round trip)
    #pragma unroll
    for (int i = 0; i < 7; ++i) {
        int linear = tid + i * NTHREADS;   // < 1792
        int r = linear / NFEAT;
        int f = linear - r * NFEAT;
        int v;
        if (f == 0)      v = __ldg(user_ids + row0 + r);
        else if (f == 1) v = __ldg(item_ids + row0 + r);
        else             v = __ldg(sparse + (size_t)(row0 + r) * NSP + (f - 2));
        sIdx[r * NFEAT + f] = v;
    }
    __syncthreads();

    // accumulators: warp covers 16 rows x 64 cols = 8 m16n8 tiles
    float c[8][4];
    #pragma unroll
    for (int nt = 0; nt < 8; ++nt) {
        c[nt][0] = 0.f; c[nt][1] = 0.f; c[nt][2] = 0.f; c[nt][3] = 0.f;
    }

    // ---- cp.async prefetch of one feature (A gather fp32 + W1T B tile bf16)
    auto prefetch = [&](int f, int st) {
        float* A = sA + st * TILE_M * A_STR;
        #pragma unroll
        for (int i = 0; i < 4; ++i) {
            int linear = tid + i * NTHREADS;   // 0..1023
            int r  = linear >> 4;              // local row
            int ch = linear & 15;              // float4 chunk
            int idx = sIdx[r * NFEAT + f];
            const float* src;
            if (f == 0)      src = user_emb + (size_t)idx * EMB;
            else if (f == 1) src = item_emb + (size_t)idx * EMB;
            else             src = sparse_tables + ((size_t)(f - 2) * SPVOC + (size_t)idx) * EMB;
            cpa16(A + r * A_STR + ch * 4, src + ch * 4);
        }
        __nv_bfloat16* Bst = sB + st * NDIM * B_STR;
        const __nv_bfloat16* bsrc = g_W1T + f * EMB;
        #pragma unroll
        for (int i = 0; i < 4; ++i) {
            int linear = tid + i * NTHREADS;
            int n  = linear >> 3;
            int ch = linear & 7;
            cpa16(Bst + n * B_STR + ch * 8, bsrc + (size_t)n * KDIM + ch * 8);
        }
        cpa_commit();
    };

    // ---- MMA over one staged feature (K = 64, 4 k-steps of m16n8k16)
    auto do_mma = [&](int st) {
        const float* A = sA + st * TILE_M * A_STR;
        const __nv_bfloat16* Bst = sB + st * NDIM * B_STR;
        #pragma unroll
        for (int ks = 0; ks < 4; ++ks) {
            const float* ar0 = A + (mrow + g)     * A_STR + ks * 16 + 2 * tg;
            const float* ar1 = A + (mrow + g + 8) * A_STR + ks * 16 + 2 * tg;
            float2 v0 = *(const float2*)ar0;
            float2 v1 = *(const float2*)ar1;
            float2 v2 = *(const float2*)(ar0 + 8);
            float2 v3 = *(const float2*)(ar1 + 8);
            uint32_t a0 = pack_bf16x2(v0.x, v0.y);
            uint32_t a1 = pack_bf16x2(v1.x, v1.y);
            uint32_t a2 = pack_bf16x2(v2.x, v2.y);
            uint32_t a3 = pack_bf16x2(v3.x, v3.y);
            #pragma unroll
            for (int nt = 0; nt < 8; ++nt) {
                const __nv_bfloat16* bp = Bst + (nh * 64 + nt * 8 + g) * B_STR + ks * 16 + 2 * tg;
                uint32_t b0  = *(const uint32_t*)bp;
                uint32_t b1r = *(const uint32_t*)(bp + 8);
                asm volatile(
                    "mma.sync.aligned.m16n8k16.row.col.f32.bf16.bf16.f32 "
                    "{%0,%1,%2,%3}, {%4,%5,%6,%7}, {%8,%9}, {%0,%1,%2,%3};\n"
                    : "+f"(c[nt][0]), "+f"(c[nt][1]), "+f"(c[nt][2]), "+f"(c[nt][3])
                    : "r"(a0), "r"(a1), "r"(a2), "r"(a3), "r"(b0), "r"(b1r));
            }
        }
    };

    // ---- 2-stage software pipeline over the 28 features
    prefetch(0, 0);
    prefetch(1, 1);

    for (int f = 0; f < NFEAT; ++f) {
        if (f == NFEAT - 1) cpa_wait0(); else cpa_wait1();
        __syncthreads();               // stage f&1 fully visible to all warps
        do_mma(f & 1);
        __syncthreads();               // all warps done reading before overwrite
        if (f + 2 < NFEAT) prefetch(f + 2, f & 1);
    }

    // ---- Epilogue: bias + ReLU + dot(W2) partial per n-half
    float acc0 = 0.f, acc1 = 0.f;      // rows (mrow+g), (mrow+g+8)
    #pragma unroll
    for (int nt = 0; nt < 8; ++nt) {
        int n0 = nh * 64 + nt * 8 + 2 * tg;
        float bias0 = __ldg(b1 + n0);
        float bias1 = __ldg(b1 + n0 + 1);
        float w0 = __ldg(W2 + n0);
        float w1 = __ldg(W2 + n0 + 1);
        acc0 += fmaxf(c[nt][0] + bias0, 0.f) * w0;
        acc0 += fmaxf(c[nt][1] + bias1, 0.f) * w1;
        acc1 += fmaxf(c[nt][2] + bias0, 0.f) * w0;
        acc1 += fmaxf(c[nt][3] + bias1, 0.f) * w1;
    }
    acc0 += __shfl_xor_sync(0xffffffffu, acc0, 1);
    acc0 += __shfl_xor_sync(0xffffffffu, acc0, 2);
    acc1 += __shfl_xor_sync(0xffffffffu, acc1, 1);
    acc1 += __shfl_xor_sync(0xffffffffu, acc1, 2);

    if (tg == 0) {
        sPart[(mrow + g)     * 2 + nh] = acc0;
        sPart[(mrow + g + 8) * 2 + nh] = acc1;
    }
    __syncthreads();

    if (tid < TILE_M) {
        float x = sPart[tid * 2] + sPart[tid * 2 + 1] + __ldg(b2);
        out[row0 + tid] = 1.f / (1.f + __expf(-x));
    }
}

extern "C" void kernel_launch(void* const* d_in, const int* in_sizes, int n_in,
                              void* d_out, int out_size) {
    const int*   user_ids      = (const int*)d_in[0];
    const int*   item_ids      = (const int*)d_in[1];
    const int*   sparse        = (const int*)d_in[2];
    const float* user_emb      = (const float*)d_in[3];
    const float* item_emb      = (const float*)d_in[4];
    const float* sparse_tables = (const float*)d_in[5];
    const float* W1            = (const float*)d_in[6];
    const float* b1            = (const float*)d_in[7];
    const float* W2            = (const float*)d_in[8];
    const float* b2            = (const float*)d_in[9];
    float* out = (float*)d_out;

    cudaFuncSetAttribute(dlrm_fused_kernel,
                         cudaFuncAttributeMaxDynamicSharedMemorySize, SMEM_TOTAL);

    prep_w1_kernel<<<(NDIM * KDIM + 255) / 256, 256>>>(W1);
    dlrm_fused_kernel<<<BATCH / TILE_M, NTHREADS, SMEM_TOTAL>>>(
        user_ids, item_ids, sparse, user_emb, item_emb, sparse_tables,
        b1, W2, b2, out);
}